// round 5
// baseline (speedup 1.0000x reference)
#include <cuda_runtime.h>
#include <math.h>

#define NN 100000
#define EE 1200000
#define GG 128

// ---------------- device scratch (no allocations allowed) ----------------
__device__ float g_bufA[NN * 64];
__device__ float g_bufB[NN * 64];
__device__ int   g_counts[NN];        // real (non-self) edges per dst (zero at start; re-zeroed by k_cleanup)
__device__ int   g_counter[NN];
__device__ int   g_ptr[NN];           // CSR row start (block-local excl scan)
__device__ int   g_csr[EE];           // src ids bucketed by dst
__device__ int   g_bsums[512];
__device__ float g_dinv[NN];
__device__ float g_bnsum[3][64];      // per-layer BN stats (zero at start; re-zeroed by k_cleanup)
__device__ float g_bnsq[3][64];
__device__ float g_Wc[64 * 64];
__device__ float g_bc[64];

// packed fp32x2 FMA (Blackwell)
__device__ __forceinline__ float2 ffma2(float2 a, float2 b, float2 c) {
    float2 d;
    asm("{\n\t"
        ".reg .b64 ra, rb, rc;\n\t"
        "mov.b64 ra, {%2, %3};\n\t"
        "mov.b64 rb, {%4, %5};\n\t"
        "mov.b64 rc, {%6, %7};\n\t"
        "fma.rn.f32x2 rc, ra, rb, rc;\n\t"
        "mov.b64 {%0, %1}, rc;\n\t"
        "}"
        : "=f"(d.x), "=f"(d.y)
        : "f"(a.x), "f"(a.y), "f"(b.x), "f"(b.y), "f"(c.x), "f"(c.y));
    return d;
}

// ---------------- CSR build ----------------
__global__ void k_hist(const int* __restrict__ ei) {
    int i = blockIdx.x * 256 + threadIdx.x;
    if (i < EE / 4) {
        int4 d = reinterpret_cast<const int4*>(ei + EE)[i];
        atomicAdd(&g_counts[d.x], 1);
        atomicAdd(&g_counts[d.y], 1);
        atomicAdd(&g_counts[d.z], 1);
        atomicAdd(&g_counts[d.w], 1);
    }
}

__device__ __forceinline__ int warp_incl(int v, int lane) {
    #pragma unroll
    for (int o = 1; o < 32; o <<= 1) {
        int t = __shfl_up_sync(0xFFFFFFFFu, v, o);
        if (lane >= o) v += t;
    }
    return v;
}

template <int NW>
__device__ __forceinline__ int block_excl_scan(int v, int tid, int* total) {
    __shared__ int wt[NW];
    int lane = tid & 31, wid = tid >> 5;
    int incl = warp_incl(v, lane);
    if (lane == 31) wt[wid] = incl;
    __syncthreads();
    if (wid == 0) {
        int x = (lane < NW) ? wt[lane] : 0;
        x = warp_incl(x, lane);
        if (lane < NW) wt[lane] = x;
    }
    __syncthreads();
    int off = wid ? wt[wid - 1] : 0;
    *total = wt[NW - 1];
    return off + incl - v;
}

__global__ void k_scan1() {
    int tid = threadIdx.x;
    int i = blockIdx.x * 256 + tid;
    int v = (i < NN) ? g_counts[i] : 0;     // real edges
    if (i < NN) {
        g_dinv[i] = rsqrtf((float)(v + 1)); // +1 self loop
        g_counter[i] = 0;
    }
    int total;
    int e = block_excl_scan<8>(v, tid, &total);
    if (i < NN) g_ptr[i] = e;
    if (tid == 0) g_bsums[blockIdx.x] = total;
}

__global__ void k_scan2(int nb) {
    int tid = threadIdx.x;
    int v = (tid < nb) ? g_bsums[tid] : 0;
    int total;
    int e = block_excl_scan<16>(v, tid, &total);
    if (tid < nb) g_bsums[tid] = e;
}

__global__ void k_fill(const int* __restrict__ ei) {
    int i = blockIdx.x * 256 + threadIdx.x;
    if (i < EE / 4) {
        int4 d = reinterpret_cast<const int4*>(ei + EE)[i];
        int4 s = reinterpret_cast<const int4*>(ei)[i];
        int p;
        p = g_ptr[d.x] + g_bsums[d.x >> 8] + atomicAdd(&g_counter[d.x], 1); g_csr[p] = s.x;
        p = g_ptr[d.y] + g_bsums[d.y >> 8] + atomicAdd(&g_counter[d.y], 1); g_csr[p] = s.y;
        p = g_ptr[d.z] + g_bsums[d.z >> 8] + atomicAdd(&g_counter[d.z], 1); g_csr[p] = s.z;
        p = g_ptr[d.w] + g_bsums[d.w >> 8] + atomicAdd(&g_counter[d.w], 1); g_csr[p] = s.w;
    }
}

// ------ GEMM: bufB = act(hin) @ W (+bias) [conv path: * dinv[row]] ------
__global__ __launch_bounds__(256) void k_gemm(
    const float* __restrict__ xin,
    const float* __restrict__ Wext,
    const float* __restrict__ gma,
    const float* __restrict__ bta,
    int src0, int use_wc, int bn_layer,   // bn_layer < 0: no activation
    float* __restrict__ emb_out)
{
    const float* hin = src0 ? xin : g_bufA;
    const float* W   = use_wc ? g_Wc : Wext;
    float*       out = g_bufB;

    int j  = threadIdx.x;   // feature/col 0..63
    int ty = threadIdx.y;   // 0..3 rows per iter

    float2 wcol[32];        // W column j, paired over k
    #pragma unroll
    for (int k2 = 0; k2 < 32; k2++)
        wcol[k2] = make_float2(W[(2 * k2) * 64 + j], W[(2 * k2 + 1) * 64 + j]);

    float sc = 1.f, sh = 0.f;
    if (bn_layer >= 0) {
        float mu   = g_bnsum[bn_layer][j] * (1.0f / NN);
        float var  = g_bnsq[bn_layer][j] * (1.0f / NN) - mu * mu;
        float istd = rsqrtf(var + 1e-5f);
        sc = istd * gma[j];
        sh = bta[j] - mu * sc;
    }
    float b = use_wc ? g_bc[j] : 0.f;
    const int scale_dinv = !use_wc;

    __shared__ float rows[2][4][64];
    const int STRIDE = gridDim.x * 4;
    int r0 = blockIdx.x * 4;
    {
        int r = r0 + ty;
        float v = hin[r * 64 + j];
        if (bn_layer >= 0) v = fmaxf(v * sc + sh, 0.f);
        rows[0][ty][j] = v;
        if (emb_out) emb_out[r * 64 + j] = v;
    }
    __syncthreads();
    int buf = 0;
    for (; r0 < NN; r0 += STRIDE) {
        int rn0 = r0 + STRIDE;
        float vn = 0.f;
        if (rn0 < NN) {
            int rn = rn0 + ty;
            vn = hin[rn * 64 + j];
            if (bn_layer >= 0) vn = fmaxf(vn * sc + sh, 0.f);
            if (emb_out) emb_out[rn * 64 + j] = vn;
        }
        const float2* rp = reinterpret_cast<const float2*>(rows[buf][ty]);
        float2 a0 = make_float2(0.f, 0.f), a1 = make_float2(0.f, 0.f);
        #pragma unroll
        for (int k2 = 0; k2 < 16; k2++) {
            a0 = ffma2(rp[2 * k2],     wcol[2 * k2],     a0);
            a1 = ffma2(rp[2 * k2 + 1], wcol[2 * k2 + 1], a1);
        }
        int r = r0 + ty;
        float res = (a0.x + a1.x) + (a0.y + a1.y) + b;
        if (scale_dinv) res *= g_dinv[r];
        out[r * 64 + j] = res;
        if (rn0 < NN) rows[buf ^ 1][ty][j] = vn;
        __syncthreads();
        buf ^= 1;
    }
}

// ---- aggregation: 2 warps per node (32 features each, 1 cache line/gather) ----
// bufA[d] = dinv[d] * (sum_{s in N(d)} hS[s] + hS[d]) + bias ; hS prescaled by dinv.
__global__ __launch_bounds__(256) void k_agg(const float* __restrict__ bias, int layer) {
    int lane = threadIdx.x & 31;
    int wrp  = threadIdx.x >> 5;             // 0..7
    int gw   = blockIdx.x * 8 + wrp;         // global warp
    int half = gw & 1;
    int f    = half * 32 + lane;             // feature 0..63
    const float* __restrict__ h = g_bufB;
    float* ao = g_bufA;
    float bb = bias[f];
    float psum = 0.f, psq = 0.f;
    int node0  = gw >> 1;
    int stride = (gridDim.x * 8) >> 1;

    for (int node = node0; node < NN; node += stride) {
        int beg = g_ptr[node] + g_bsums[node >> 8];
        int cnt = g_counts[node];
        float di = g_dinv[node];
        int m = cnt < 16 ? cnt : 16;

        // phase 1: index prefetch (predicated; no traffic beyond m)
        int idx[16];
        #pragma unroll
        for (int t = 0; t < 16; t++)
            if (t < m) idx[t] = g_csr[beg + t];

        // phase 2: up to 16 independent gathers (MLP=16)
        float v[16];
        #pragma unroll
        for (int t = 0; t < 16; t++)
            v[t] = (t < m) ? h[idx[t] * 64 + f] : 0.f;

        float a0 = 0.f, a1 = 0.f, a2 = 0.f, a3 = 0.f;
        #pragma unroll
        for (int t = 0; t < 16; t += 4) {
            a0 += v[t]; a1 += v[t + 1]; a2 += v[t + 2]; a3 += v[t + 3];
        }
        // tail: degree > 16 (rare)
        for (int t = 16; t < cnt; t++) {
            int s = g_csr[beg + t];
            a0 += h[s * 64 + f];
        }
        float hs = h[node * 64 + f];           // self term (pre-scaled)
        float acc = ((a0 + a1) + (a2 + a3)) + hs;
        acc = di * acc + bb;
        ao[node * 64 + f] = acc;
        psum += acc;
        psq  += acc * acc;
    }

    __shared__ float ssum[64], ssq[64];
    if (threadIdx.x < 64) { ssum[threadIdx.x] = 0.f; ssq[threadIdx.x] = 0.f; }
    __syncthreads();
    atomicAdd(&ssum[f], psum);
    atomicAdd(&ssq[f],  psq);
    __syncthreads();
    if (threadIdx.x < 64) {
        atomicAdd(&g_bnsum[layer][threadIdx.x], ssum[threadIdx.x]);
        atomicAdd(&g_bnsq[layer][threadIdx.x],  ssq[threadIdx.x]);
    }
}

// ---------------- Wc = fc1_w @ fc2_w ; bc = fc1_b @ fc2_w + fc2_b ----------------
__global__ void k_combine(const float* __restrict__ fc1w, const float* __restrict__ fc1b,
                          const float* __restrict__ fc2w, const float* __restrict__ fc2b) {
    int idx = blockIdx.x * 256 + threadIdx.x;
    if (idx < 4096) {
        int k = idx >> 6, j = idx & 63;
        float s = 0.f;
        #pragma unroll
        for (int t = 0; t < 64; t++) s += fc1w[k * 64 + t] * fc2w[t * 64 + j];
        g_Wc[idx] = s;
    }
    if (idx < 64) {
        float s = fc2b[idx];
        for (int t = 0; t < 64; t++) s += fc1b[t] * fc2w[t * 64 + idx];
        g_bc[idx] = s;
    }
}

// ---------------- segment max over sorted batch + fused logits ----------------
__global__ void k_segmax(const int* __restrict__ batch,
                         const float* __restrict__ fc3w, const float* __restrict__ fc3b,
                         float* __restrict__ ge, float* __restrict__ logits) {
    int g = blockIdx.x;
    int j = threadIdx.x, ty = threadIdx.y;     // (64,4)
    int lo = 0, hi = NN;
    while (lo < hi) { int m = (lo + hi) >> 1; if (batch[m] < g) lo = m + 1; else hi = m; }
    int start = lo;
    hi = NN;
    while (lo < hi) { int m = (lo + hi) >> 1; if (batch[m] < g + 1) lo = m + 1; else hi = m; }
    int end = lo;
    float mv = -INFINITY;
    for (int r = start + ty; r < end; r += 4)
        mv = fmaxf(mv, g_bufB[r * 64 + j]);
    __shared__ float red[4][64];
    red[ty][j] = mv;
    __syncthreads();
    if (ty == 0) {
        mv = fmaxf(fmaxf(red[0][j], red[1][j]), fmaxf(red[2][j], red[3][j]));
        ge[g * 64 + j] = mv;
        red[0][j] = mv;
    }
    __syncthreads();
    if (ty == 0 && j < 32) {
        float v0 = red[0][j], v1 = red[0][j + 32];
        float p0 = v0 * fc3w[2 * j]     + v1 * fc3w[2 * (j + 32)];
        float p1 = v0 * fc3w[2 * j + 1] + v1 * fc3w[2 * (j + 32) + 1];
        #pragma unroll
        for (int o = 16; o; o >>= 1) {
            p0 += __shfl_down_sync(0xFFFFFFFFu, p0, o);
            p1 += __shfl_down_sync(0xFFFFFFFFu, p1, o);
        }
        if (j == 0) {
            float l0 = p0 + fc3b[0], l1 = p1 + fc3b[1];
            float m = fmaxf(l0, l1);
            float lse = m + logf(expf(l0 - m) + expf(l1 - m));
            logits[g * 2]     = l0 - lse;
            logits[g * 2 + 1] = l1 - lse;
        }
    }
}

// zero counts + BN stats for the NEXT invocation (identical work every call)
__global__ void k_cleanup() {
    int i = blockIdx.x * 256 + threadIdx.x;
    if (i < NN) g_counts[i] = 0;
    if (blockIdx.x == 0 && threadIdx.x < 192) {
        ((float*)g_bnsum)[threadIdx.x] = 0.f;
        ((float*)g_bnsq)[threadIdx.x]  = 0.f;
    }
}

// ---------------- launch ----------------
extern "C" void kernel_launch(void* const* d_in, const int* in_sizes, int n_in,
                              void* d_out, int out_size) {
    const float* x      = (const float*)d_in[0];
    const int*   ei     = (const int*)d_in[1];
    const int*   batch  = (const int*)d_in[2];
    const float* conv_w = (const float*)d_in[3];
    const float* conv_b = (const float*)d_in[4];
    const float* bn_g   = (const float*)d_in[5];
    const float* bn_b   = (const float*)d_in[6];
    const float* fc1w   = (const float*)d_in[7];
    const float* fc1b   = (const float*)d_in[8];
    const float* fc2w   = (const float*)d_in[9];
    const float* fc2b   = (const float*)d_in[10];
    const float* fc3w   = (const float*)d_in[11];
    const float* fc3b   = (const float*)d_in[12];

    float* out     = (float*)d_out;
    float* emb_out = out;                         // [N,64]
    float* ge_out  = out + (size_t)NN * 64;       // [G,64]
    float* logits  = ge_out + (size_t)GG * 64;    // [G,2]

    const int NB_N  = (NN + 255) / 256;           // 391
    const int NB_E4 = (EE / 4 + 255) / 256;       // 1172
    dim3 b64x4(64, 4);

    k_hist<<<NB_E4, 256>>>(ei);
    k_scan1<<<NB_N, 256>>>();
    k_scan2<<<1, 512>>>(NB_N);
    // launch #4 (profiled slot): first conv GEMM — no CSR dependency
    k_gemm<<<444, b64x4>>>(x, conv_w, nullptr, nullptr, 1, 0, -1, nullptr);
    k_fill<<<NB_E4, 256>>>(ei);
    k_agg<<<888, 256>>>(conv_b, 0);

    for (int l = 1; l < 3; l++) {
        k_gemm<<<444, b64x4>>>(x, conv_w + l * 4096,
                               bn_g + (l - 1) * 64, bn_b + (l - 1) * 64,
                               0, 0, l - 1, nullptr);
        k_agg<<<888, 256>>>(conv_b + l * 64, l);
    }
    k_combine<<<16, 256>>>(fc1w, fc1b, fc2w, fc2b);
    k_gemm<<<444, b64x4>>>(x, nullptr, bn_g + 2 * 64, bn_b + 2 * 64, 0, 1, 2, emb_out);
    k_segmax<<<GG, b64x4>>>(batch, fc3w, fc3b, ge_out, logits);
    k_cleanup<<<NB_N, 256>>>();
}

// round 9
// speedup vs baseline: 1.4880x; 1.4880x over previous
#include <cuda_runtime.h>
#include <math.h>

#define NN 100000
#define EE 1200000
#define GG 128

// ---------------- device scratch (no allocations allowed) ----------------
__device__ __align__(16) float g_bufA[NN * 64];
__device__ __align__(16) float g_bufB[NN * 64];
__device__ int   g_counts[NN];        // real edges per dst (zero at start; re-zeroed by k_cleanup)
__device__ int   g_counter[NN];
__device__ int   g_ptr[NN];
__device__ int   g_csr[EE];
__device__ int   g_bsums[512];
__device__ float g_dinv[NN];
__device__ float g_bnsum[3][64];      // per-layer BN stats (zero at start; re-zeroed by k_cleanup)
__device__ float g_bnsq[3][64];
__device__ __align__(16) float g_Wc[64 * 64];
__device__ __align__(16) float g_bc[64];

// packed fp32x2 FMA (Blackwell)
__device__ __forceinline__ float2 ffma2(float2 a, float2 b, float2 c) {
    float2 d;
    asm("{\n\t"
        ".reg .b64 ra, rb, rc;\n\t"
        "mov.b64 ra, {%2, %3};\n\t"
        "mov.b64 rb, {%4, %5};\n\t"
        "mov.b64 rc, {%6, %7};\n\t"
        "fma.rn.f32x2 rc, ra, rb, rc;\n\t"
        "mov.b64 {%0, %1}, rc;\n\t"
        "}"
        : "=f"(d.x), "=f"(d.y)
        : "f"(a.x), "f"(a.y), "f"(b.x), "f"(b.y), "f"(c.x), "f"(c.y));
    return d;
}

// ---------------- CSR build ----------------
__global__ void k_hist(const int* __restrict__ ei) {
    int i = blockIdx.x * 256 + threadIdx.x;
    if (i < EE / 4) {
        int4 d = reinterpret_cast<const int4*>(ei + EE)[i];
        atomicAdd(&g_counts[d.x], 1);
        atomicAdd(&g_counts[d.y], 1);
        atomicAdd(&g_counts[d.z], 1);
        atomicAdd(&g_counts[d.w], 1);
    }
}

__device__ __forceinline__ int warp_incl(int v, int lane) {
    #pragma unroll
    for (int o = 1; o < 32; o <<= 1) {
        int t = __shfl_up_sync(0xFFFFFFFFu, v, o);
        if (lane >= o) v += t;
    }
    return v;
}

template <int NW>
__device__ __forceinline__ int block_excl_scan(int v, int tid, int* total) {
    __shared__ int wt[NW];
    int lane = tid & 31, wid = tid >> 5;
    int incl = warp_incl(v, lane);
    if (lane == 31) wt[wid] = incl;
    __syncthreads();
    if (wid == 0) {
        int x = (lane < NW) ? wt[lane] : 0;
        x = warp_incl(x, lane);
        if (lane < NW) wt[lane] = x;
    }
    __syncthreads();
    int off = wid ? wt[wid - 1] : 0;
    *total = wt[NW - 1];
    return off + incl - v;
}

__global__ void k_scan1() {
    int tid = threadIdx.x;
    int i = blockIdx.x * 256 + tid;
    int v = (i < NN) ? g_counts[i] : 0;
    if (i < NN) {
        g_dinv[i] = rsqrtf((float)(v + 1)); // +1 self loop
        g_counter[i] = 0;
    }
    int total;
    int e = block_excl_scan<8>(v, tid, &total);
    if (i < NN) g_ptr[i] = e;
    if (tid == 0) g_bsums[blockIdx.x] = total;
}

__global__ void k_scan2(int nb) {
    int tid = threadIdx.x;
    int v = (tid < nb) ? g_bsums[tid] : 0;
    int total;
    int e = block_excl_scan<16>(v, tid, &total);
    if (tid < nb) g_bsums[tid] = e;
}

__global__ void k_fill(const int* __restrict__ ei) {
    int i = blockIdx.x * 256 + threadIdx.x;
    if (i < EE / 4) {
        int4 d = reinterpret_cast<const int4*>(ei + EE)[i];
        int4 s = reinterpret_cast<const int4*>(ei)[i];
        int p;
        p = g_ptr[d.x] + g_bsums[d.x >> 8] + atomicAdd(&g_counter[d.x], 1); g_csr[p] = s.x;
        p = g_ptr[d.y] + g_bsums[d.y >> 8] + atomicAdd(&g_counter[d.y], 1); g_csr[p] = s.y;
        p = g_ptr[d.z] + g_bsums[d.z >> 8] + atomicAdd(&g_counter[d.z], 1); g_csr[p] = s.z;
        p = g_ptr[d.w] + g_bsums[d.w >> 8] + atomicAdd(&g_counter[d.w], 1); g_csr[p] = s.w;
    }
}

// ------ register-tiled GEMM: bufB = act(hin) @ W (+bias) [conv: * dinv[row]] ------
// Block tile 64x64, warp tile 32x16, thread tile 4x4 (f32x2 paired over K).
__global__ __launch_bounds__(256, 3) void k_gemm(
    const float* __restrict__ xin,
    const float* __restrict__ Wext,
    const float* __restrict__ gma,
    const float* __restrict__ bta,
    int src0, int use_wc, int bn_layer,   // bn_layer < 0: no activation
    float* __restrict__ emb_out)
{
    const float* __restrict__ hin = src0 ? xin : g_bufA;
    const float* __restrict__ W   = use_wc ? g_Wc : Wext;
    float* __restrict__ out = g_bufB;

    __shared__ float hs[64][68];   // pad 68: conflict-free f2 a-loads, f4-aligned stage
    __shared__ float Wt[64][66];   // transposed weights, pad 66: conflict-free b-loads

    int tid = threadIdx.x;

    // stage transposed weights: Wt[c][k] = W[k][c]
    #pragma unroll
    for (int t = 0; t < 16; t++) {
        int idx = tid + t * 256;
        Wt[idx & 63][idx >> 6] = W[idx];
    }

    // BN scale/shift for the 4 input columns this thread stages
    int cq = (tid & 15) * 4;
    float sc0 = 1.f, sc1 = 1.f, sc2 = 1.f, sc3 = 1.f;
    float sh0 = 0.f, sh1 = 0.f, sh2 = 0.f, sh3 = 0.f;
    if (bn_layer >= 0) {
        float mu, var, istd;
        mu = g_bnsum[bn_layer][cq] * (1.0f / NN);
        var = g_bnsq[bn_layer][cq] * (1.0f / NN) - mu * mu;
        istd = rsqrtf(var + 1e-5f); sc0 = istd * gma[cq];     sh0 = bta[cq]     - mu * sc0;
        mu = g_bnsum[bn_layer][cq + 1] * (1.0f / NN);
        var = g_bnsq[bn_layer][cq + 1] * (1.0f / NN) - mu * mu;
        istd = rsqrtf(var + 1e-5f); sc1 = istd * gma[cq + 1]; sh1 = bta[cq + 1] - mu * sc1;
        mu = g_bnsum[bn_layer][cq + 2] * (1.0f / NN);
        var = g_bnsq[bn_layer][cq + 2] * (1.0f / NN) - mu * mu;
        istd = rsqrtf(var + 1e-5f); sc2 = istd * gma[cq + 2]; sh2 = bta[cq + 2] - mu * sc2;
        mu = g_bnsum[bn_layer][cq + 3] * (1.0f / NN);
        var = g_bnsq[bn_layer][cq + 3] * (1.0f / NN) - mu * mu;
        istd = rsqrtf(var + 1e-5f); sc3 = istd * gma[cq + 3]; sh3 = bta[cq + 3] - mu * sc3;
    }

    // stage input tile (64 rows x 64 cols), fused BN+ReLU, optional emb_out
    int r0 = blockIdx.x * 64;
    int srow = tid >> 4;              // 0..15; rows srow + 16*i
    #pragma unroll
    for (int i = 0; i < 4; i++) {
        int row = srow + 16 * i;
        int r = r0 + row;
        if (r < NN) {
            float4 v = *reinterpret_cast<const float4*>(&hin[r * 64 + cq]);
            if (bn_layer >= 0) {
                v.x = fmaxf(v.x * sc0 + sh0, 0.f);
                v.y = fmaxf(v.y * sc1 + sh1, 0.f);
                v.z = fmaxf(v.z * sc2 + sh2, 0.f);
                v.w = fmaxf(v.w * sc3 + sh3, 0.f);
            }
            *reinterpret_cast<float4*>(&hs[row][cq]) = v;
            if (emb_out) *reinterpret_cast<float4*>(&emb_out[r * 64 + cq]) = v;
        }
    }
    __syncthreads();

    // outer-product compute
    int w = tid >> 5, lane = tid & 31;
    int ry = lane >> 2, cx = lane & 3;
    int rbase = (w & 1) * 32 + ry;          // thread rows: rbase + 8*i
    int c0 = (w >> 1) * 16 + cx * 4;        // thread cols: c0..c0+3

    float2 acc[4][4];
    #pragma unroll
    for (int i = 0; i < 4; i++)
        #pragma unroll
        for (int j = 0; j < 4; j++)
            acc[i][j] = make_float2(0.f, 0.f);

    #pragma unroll 4
    for (int k2 = 0; k2 < 32; k2++) {
        float2 a0 = *reinterpret_cast<const float2*>(&hs[rbase][2 * k2]);
        float2 a1 = *reinterpret_cast<const float2*>(&hs[rbase + 8][2 * k2]);
        float2 a2 = *reinterpret_cast<const float2*>(&hs[rbase + 16][2 * k2]);
        float2 a3 = *reinterpret_cast<const float2*>(&hs[rbase + 24][2 * k2]);
        float2 b0 = *reinterpret_cast<const float2*>(&Wt[c0][2 * k2]);
        float2 b1 = *reinterpret_cast<const float2*>(&Wt[c0 + 1][2 * k2]);
        float2 b2 = *reinterpret_cast<const float2*>(&Wt[c0 + 2][2 * k2]);
        float2 b3 = *reinterpret_cast<const float2*>(&Wt[c0 + 3][2 * k2]);
        acc[0][0] = ffma2(a0, b0, acc[0][0]); acc[0][1] = ffma2(a0, b1, acc[0][1]);
        acc[0][2] = ffma2(a0, b2, acc[0][2]); acc[0][3] = ffma2(a0, b3, acc[0][3]);
        acc[1][0] = ffma2(a1, b0, acc[1][0]); acc[1][1] = ffma2(a1, b1, acc[1][1]);
        acc[1][2] = ffma2(a1, b2, acc[1][2]); acc[1][3] = ffma2(a1, b3, acc[1][3]);
        acc[2][0] = ffma2(a2, b0, acc[2][0]); acc[2][1] = ffma2(a2, b1, acc[2][1]);
        acc[2][2] = ffma2(a2, b2, acc[2][2]); acc[2][3] = ffma2(a2, b3, acc[2][3]);
        acc[3][0] = ffma2(a3, b0, acc[3][0]); acc[3][1] = ffma2(a3, b1, acc[3][1]);
        acc[3][2] = ffma2(a3, b2, acc[3][2]); acc[3][3] = ffma2(a3, b3, acc[3][3]);
    }

    float4 bb = make_float4(0.f, 0.f, 0.f, 0.f);
    if (use_wc) bb = *reinterpret_cast<const float4*>(&g_bc[c0]);
    const int scale_dinv = !use_wc;

    #pragma unroll
    for (int i = 0; i < 4; i++) {
        int r = r0 + rbase + 8 * i;
        if (r < NN) {
            float dv = scale_dinv ? g_dinv[r] : 1.f;
            float4 o;
            o.x = (acc[i][0].x + acc[i][0].y + bb.x) * dv;
            o.y = (acc[i][1].x + acc[i][1].y + bb.y) * dv;
            o.z = (acc[i][2].x + acc[i][2].y + bb.z) * dv;
            o.w = (acc[i][3].x + acc[i][3].y + bb.w) * dv;
            *reinterpret_cast<float4*>(&out[r * 64 + c0]) = o;
        }
    }
}

// ---- aggregation: 2 warps per node (32 features each, 1 cache line/gather) ----
__global__ __launch_bounds__(256) void k_agg(const float* __restrict__ bias, int layer) {
    int lane = threadIdx.x & 31;
    int wrp  = threadIdx.x >> 5;
    int gw   = blockIdx.x * 8 + wrp;
    int half = gw & 1;
    int f    = half * 32 + lane;
    const float* __restrict__ h = g_bufB;
    float* ao = g_bufA;
    float bb = bias[f];
    float psum = 0.f, psq = 0.f;
    int node0  = gw >> 1;
    int stride = (gridDim.x * 8) >> 1;

    for (int node = node0; node < NN; node += stride) {
        int beg = g_ptr[node] + g_bsums[node >> 8];
        int cnt = g_counts[node];
        float di = g_dinv[node];
        int m = cnt < 16 ? cnt : 16;

        int idx[16];
        #pragma unroll
        for (int t = 0; t < 16; t++)
            if (t < m) idx[t] = g_csr[beg + t];

        float v[16];
        #pragma unroll
        for (int t = 0; t < 16; t++)
            v[t] = (t < m) ? h[idx[t] * 64 + f] : 0.f;

        float a0 = 0.f, a1 = 0.f, a2 = 0.f, a3 = 0.f;
        #pragma unroll
        for (int t = 0; t < 16; t += 4) {
            a0 += v[t]; a1 += v[t + 1]; a2 += v[t + 2]; a3 += v[t + 3];
        }
        for (int t = 16; t < cnt; t++) {
            int s = g_csr[beg + t];
            a0 += h[s * 64 + f];
        }
        float hs = h[node * 64 + f];
        float acc = ((a0 + a1) + (a2 + a3)) + hs;
        acc = di * acc + bb;
        ao[node * 64 + f] = acc;
        psum += acc;
        psq  += acc * acc;
    }

    __shared__ float ssum[64], ssq[64];
    if (threadIdx.x < 64) { ssum[threadIdx.x] = 0.f; ssq[threadIdx.x] = 0.f; }
    __syncthreads();
    atomicAdd(&ssum[f], psum);
    atomicAdd(&ssq[f],  psq);
    __syncthreads();
    if (threadIdx.x < 64) {
        atomicAdd(&g_bnsum[layer][threadIdx.x], ssum[threadIdx.x]);
        atomicAdd(&g_bnsq[layer][threadIdx.x],  ssq[threadIdx.x]);
    }
}

// ---------------- Wc = fc1_w @ fc2_w ; bc = fc1_b @ fc2_w + fc2_b ----------------
__global__ void k_combine(const float* __restrict__ fc1w, const float* __restrict__ fc1b,
                          const float* __restrict__ fc2w, const float* __restrict__ fc2b) {
    int idx = blockIdx.x * 256 + threadIdx.x;
    if (idx < 4096) {
        int k = idx >> 6, j = idx & 63;
        float s = 0.f;
        #pragma unroll
        for (int t = 0; t < 64; t++) s += fc1w[k * 64 + t] * fc2w[t * 64 + j];
        g_Wc[idx] = s;
    }
    if (idx < 64) {
        float s = fc2b[idx];
        for (int t = 0; t < 64; t++) s += fc1b[t] * fc2w[t * 64 + idx];
        g_bc[idx] = s;
    }
}

// ---------------- segment max over sorted batch + fused logits ----------------
__global__ void k_segmax(const int* __restrict__ batch,
                         const float* __restrict__ fc3w, const float* __restrict__ fc3b,
                         float* __restrict__ ge, float* __restrict__ logits) {
    int g = blockIdx.x;
    int j = threadIdx.x, ty = threadIdx.y;     // (64,4)
    int lo = 0, hi = NN;
    while (lo < hi) { int m = (lo + hi) >> 1; if (batch[m] < g) lo = m + 1; else hi = m; }
    int start = lo;
    hi = NN;
    while (lo < hi) { int m = (lo + hi) >> 1; if (batch[m] < g + 1) lo = m + 1; else hi = m; }
    int end = lo;
    float mv = -INFINITY;
    for (int r = start + ty; r < end; r += 4)
        mv = fmaxf(mv, g_bufB[r * 64 + j]);
    __shared__ float red[4][64];
    red[ty][j] = mv;
    __syncthreads();
    if (ty == 0) {
        mv = fmaxf(fmaxf(red[0][j], red[1][j]), fmaxf(red[2][j], red[3][j]));
        ge[g * 64 + j] = mv;
        red[0][j] = mv;
    }
    __syncthreads();
    if (ty == 0 && j < 32) {
        float v0 = red[0][j], v1 = red[0][j + 32];
        float p0 = v0 * fc3w[2 * j]     + v1 * fc3w[2 * (j + 32)];
        float p1 = v0 * fc3w[2 * j + 1] + v1 * fc3w[2 * (j + 32) + 1];
        #pragma unroll
        for (int o = 16; o; o >>= 1) {
            p0 += __shfl_down_sync(0xFFFFFFFFu, p0, o);
            p1 += __shfl_down_sync(0xFFFFFFFFu, p1, o);
        }
        if (j == 0) {
            float l0 = p0 + fc3b[0], l1 = p1 + fc3b[1];
            float m = fmaxf(l0, l1);
            float lse = m + logf(expf(l0 - m) + expf(l1 - m));
            logits[g * 2]     = l0 - lse;
            logits[g * 2 + 1] = l1 - lse;
        }
    }
}

// zero counts + BN stats for the NEXT invocation (identical work every call)
__global__ void k_cleanup() {
    int i = blockIdx.x * 256 + threadIdx.x;
    if (i < NN) g_counts[i] = 0;
    if (blockIdx.x == 0 && threadIdx.x < 192) {
        ((float*)g_bnsum)[threadIdx.x] = 0.f;
        ((float*)g_bnsq)[threadIdx.x]  = 0.f;
    }
}

// ---------------- launch ----------------
extern "C" void kernel_launch(void* const* d_in, const int* in_sizes, int n_in,
                              void* d_out, int out_size) {
    const float* x      = (const float*)d_in[0];
    const int*   ei     = (const int*)d_in[1];
    const int*   batch  = (const int*)d_in[2];
    const float* conv_w = (const float*)d_in[3];
    const float* conv_b = (const float*)d_in[4];
    const float* bn_g   = (const float*)d_in[5];
    const float* bn_b   = (const float*)d_in[6];
    const float* fc1w   = (const float*)d_in[7];
    const float* fc1b   = (const float*)d_in[8];
    const float* fc2w   = (const float*)d_in[9];
    const float* fc2b   = (const float*)d_in[10];
    const float* fc3w   = (const float*)d_in[11];
    const float* fc3b   = (const float*)d_in[12];

    float* out     = (float*)d_out;
    float* emb_out = out;                         // [N,64]
    float* ge_out  = out + (size_t)NN * 64;       // [G,64]
    float* logits  = ge_out + (size_t)GG * 64;    // [G,2]

    const int NB_N  = (NN + 255) / 256;           // 391
    const int NB_E4 = (EE / 4 + 255) / 256;       // 1172
    const int NB_G  = (NN + 63) / 64;             // 1563
    dim3 b64x4(64, 4);

    k_hist<<<NB_E4, 256>>>(ei);
    k_scan1<<<NB_N, 256>>>();
    k_scan2<<<1, 512>>>(NB_N);
    // profiled slot: first conv GEMM — no CSR dependency
    k_gemm<<<NB_G, 256>>>(x, conv_w, nullptr, nullptr, 1, 0, -1, nullptr);
    k_fill<<<NB_E4, 256>>>(ei);
    k_agg<<<888, 256>>>(conv_b, 0);

    for (int l = 1; l < 3; l++) {
        k_gemm<<<NB_G, 256>>>(x, conv_w + l * 4096,
                              bn_g + (l - 1) * 64, bn_b + (l - 1) * 64,
                              0, 0, l - 1, nullptr);
        k_agg<<<888, 256>>>(conv_b + l * 64, l);
    }
    k_combine<<<16, 256>>>(fc1w, fc1b, fc2w, fc2b);
    k_gemm<<<NB_G, 256>>>(x, nullptr, bn_g + 2 * 64, bn_b + 2 * 64, 0, 1, 2, emb_out);
    k_segmax<<<GG, b64x4>>>(batch, fc3w, fc3b, ge_out, logits);
    k_cleanup<<<NB_N, 256>>>();
}

// round 11
// speedup vs baseline: 1.7058x; 1.1464x over previous
#include <cuda_runtime.h>
#include <math.h>

#define NN 100000
#define EE 1200000
#define GG 128
#define NTILES ((NN + 63) / 64)

// ---------------- device scratch (no allocations allowed) ----------------
__device__ __align__(16) float g_bufA[NN * 64];
__device__ __align__(16) float g_bufB[NN * 64];
__device__ int   g_counts[NN];        // real edges per dst (zero at start; re-zeroed by k_cleanup)
__device__ int   g_counter[NN];
__device__ int   g_ptr[NN];
__device__ int   g_csr[EE];
__device__ int   g_bsums[512];
__device__ float g_dinv[NN];
__device__ float g_bnsum[3][64];      // per-layer BN stats (zero at start; re-zeroed by k_cleanup)
__device__ float g_bnsq[3][64];
__device__ __align__(16) float g_Wc[64 * 64];
__device__ __align__(16) float g_bc[64];

// packed fp32x2 FMA (Blackwell)
__device__ __forceinline__ float2 ffma2(float2 a, float2 b, float2 c) {
    float2 d;
    asm("{\n\t"
        ".reg .b64 ra, rb, rc;\n\t"
        "mov.b64 ra, {%2, %3};\n\t"
        "mov.b64 rb, {%4, %5};\n\t"
        "mov.b64 rc, {%6, %7};\n\t"
        "fma.rn.f32x2 rc, ra, rb, rc;\n\t"
        "mov.b64 {%0, %1}, rc;\n\t"
        "}"
        : "=f"(d.x), "=f"(d.y)
        : "f"(a.x), "f"(a.y), "f"(b.x), "f"(b.y), "f"(c.x), "f"(c.y));
    return d;
}

// ---------------- CSR build ----------------
__global__ void k_hist(const int* __restrict__ ei) {
    int i = blockIdx.x * 256 + threadIdx.x;
    if (i < EE / 4) {
        int4 d = reinterpret_cast<const int4*>(ei + EE)[i];
        atomicAdd(&g_counts[d.x], 1);
        atomicAdd(&g_counts[d.y], 1);
        atomicAdd(&g_counts[d.z], 1);
        atomicAdd(&g_counts[d.w], 1);
    }
}

__device__ __forceinline__ int warp_incl(int v, int lane) {
    #pragma unroll
    for (int o = 1; o < 32; o <<= 1) {
        int t = __shfl_up_sync(0xFFFFFFFFu, v, o);
        if (lane >= o) v += t;
    }
    return v;
}

template <int NW>
__device__ __forceinline__ int block_excl_scan(int v, int tid, int* total) {
    __shared__ int wt[NW];
    int lane = tid & 31, wid = tid >> 5;
    int incl = warp_incl(v, lane);
    if (lane == 31) wt[wid] = incl;
    __syncthreads();
    if (wid == 0) {
        int x = (lane < NW) ? wt[lane] : 0;
        x = warp_incl(x, lane);
        if (lane < NW) wt[lane] = x;
    }
    __syncthreads();
    int off = wid ? wt[wid - 1] : 0;
    *total = wt[NW - 1];
    return off + incl - v;
}

__global__ void k_scan1() {
    int tid = threadIdx.x;
    int i = blockIdx.x * 256 + tid;
    int v = (i < NN) ? g_counts[i] : 0;
    if (i < NN) {
        g_dinv[i] = rsqrtf((float)(v + 1)); // +1 self loop
        g_counter[i] = 0;
    }
    int total;
    int e = block_excl_scan<8>(v, tid, &total);
    if (i < NN) g_ptr[i] = e;
    if (tid == 0) g_bsums[blockIdx.x] = total;
}

__global__ void k_scan2(int nb) {
    int tid = threadIdx.x;
    int v = (tid < nb) ? g_bsums[tid] : 0;
    int total;
    int e = block_excl_scan<16>(v, tid, &total);
    if (tid < nb) g_bsums[tid] = e;
}

__global__ void k_fill(const int* __restrict__ ei) {
    int i = blockIdx.x * 256 + threadIdx.x;
    if (i < EE / 4) {
        int4 d = reinterpret_cast<const int4*>(ei + EE)[i];
        int4 s = reinterpret_cast<const int4*>(ei)[i];
        int p;
        p = g_ptr[d.x] + g_bsums[d.x >> 8] + atomicAdd(&g_counter[d.x], 1); g_csr[p] = s.x;
        p = g_ptr[d.y] + g_bsums[d.y >> 8] + atomicAdd(&g_counter[d.y], 1); g_csr[p] = s.y;
        p = g_ptr[d.z] + g_bsums[d.z >> 8] + atomicAdd(&g_counter[d.z], 1); g_csr[p] = s.z;
        p = g_ptr[d.w] + g_bsums[d.w >> 8] + atomicAdd(&g_counter[d.w], 1); g_csr[p] = s.w;
    }
}

// ------ persistent register-tiled GEMM: bufB = act(hin) @ W (+bias) ------
// Block tile 64x64, warp tile 32x16, thread tile 4x4 (f32x2 over K).
// Grid 444 = exactly 3 CTAs/SM; each block loops tiles with staged Wt.
__global__ __launch_bounds__(256, 3) void k_gemm(
    const float* __restrict__ xin,
    const float* __restrict__ Wext,
    const float* __restrict__ gma,
    const float* __restrict__ bta,
    int src0, int use_wc, int bn_layer,   // bn_layer < 0: no activation
    float* __restrict__ emb_out)
{
    const float* __restrict__ hin = src0 ? xin : g_bufA;
    const float* __restrict__ W   = use_wc ? g_Wc : Wext;
    float* __restrict__ out = g_bufB;

    __shared__ float hs[64][68];   // pad 68: conflict-free f2 a-loads, f4-aligned stage
    __shared__ float Wt[64][66];   // transposed weights, pad 66: conflict-free b-loads

    int tid = threadIdx.x;

    // stage transposed weights ONCE: Wt[c][k] = W[k][c]
    #pragma unroll
    for (int t = 0; t < 16; t++) {
        int idx = tid + t * 256;
        Wt[idx & 63][idx >> 6] = W[idx];
    }

    // BN scale/shift for the 4 input columns this thread stages
    int cq = (tid & 15) * 4;
    float sc0 = 1.f, sc1 = 1.f, sc2 = 1.f, sc3 = 1.f;
    float sh0 = 0.f, sh1 = 0.f, sh2 = 0.f, sh3 = 0.f;
    if (bn_layer >= 0) {
        float mu, var, istd;
        mu = g_bnsum[bn_layer][cq] * (1.0f / NN);
        var = g_bnsq[bn_layer][cq] * (1.0f / NN) - mu * mu;
        istd = rsqrtf(var + 1e-5f); sc0 = istd * gma[cq];     sh0 = bta[cq]     - mu * sc0;
        mu = g_bnsum[bn_layer][cq + 1] * (1.0f / NN);
        var = g_bnsq[bn_layer][cq + 1] * (1.0f / NN) - mu * mu;
        istd = rsqrtf(var + 1e-5f); sc1 = istd * gma[cq + 1]; sh1 = bta[cq + 1] - mu * sc1;
        mu = g_bnsum[bn_layer][cq + 2] * (1.0f / NN);
        var = g_bnsq[bn_layer][cq + 2] * (1.0f / NN) - mu * mu;
        istd = rsqrtf(var + 1e-5f); sc2 = istd * gma[cq + 2]; sh2 = bta[cq + 2] - mu * sc2;
        mu = g_bnsum[bn_layer][cq + 3] * (1.0f / NN);
        var = g_bnsq[bn_layer][cq + 3] * (1.0f / NN) - mu * mu;
        istd = rsqrtf(var + 1e-5f); sc3 = istd * gma[cq + 3]; sh3 = bta[cq + 3] - mu * sc3;
    }

    int w = tid >> 5, lane = tid & 31;
    int ry = lane >> 2, cx = lane & 3;
    int rbase = (w & 1) * 32 + ry;          // thread rows: rbase + 8*i
    int c0 = (w >> 1) * 16 + cx * 4;        // thread cols: c0..c0+3
    int srow = tid >> 4;                    // staging rows: srow + 16*i

    float4 bb = make_float4(0.f, 0.f, 0.f, 0.f);
    if (use_wc) bb = *reinterpret_cast<const float4*>(&g_bc[c0]);
    const int scale_dinv = !use_wc;

    for (int tile = blockIdx.x; tile < NTILES; tile += gridDim.x) {
        int r0 = tile * 64;
        __syncthreads();   // protect hs from previous tile's compute (also orders Wt on 1st iter)

        // stage input tile, fused BN+ReLU, optional emb_out
        #pragma unroll
        for (int i = 0; i < 4; i++) {
            int row = srow + 16 * i;
            int r = r0 + row;
            if (r < NN) {
                float4 v = *reinterpret_cast<const float4*>(&hin[r * 64 + cq]);
                if (bn_layer >= 0) {
                    v.x = fmaxf(v.x * sc0 + sh0, 0.f);
                    v.y = fmaxf(v.y * sc1 + sh1, 0.f);
                    v.z = fmaxf(v.z * sc2 + sh2, 0.f);
                    v.w = fmaxf(v.w * sc3 + sh3, 0.f);
                }
                *reinterpret_cast<float4*>(&hs[row][cq]) = v;
                if (emb_out) *reinterpret_cast<float4*>(&emb_out[r * 64 + cq]) = v;
            }
        }
        __syncthreads();

        float2 acc[4][4];
        #pragma unroll
        for (int i = 0; i < 4; i++)
            #pragma unroll
            for (int j = 0; j < 4; j++)
                acc[i][j] = make_float2(0.f, 0.f);

        #pragma unroll 4
        for (int k2 = 0; k2 < 32; k2++) {
            float2 a0 = *reinterpret_cast<const float2*>(&hs[rbase][2 * k2]);
            float2 a1 = *reinterpret_cast<const float2*>(&hs[rbase + 8][2 * k2]);
            float2 a2 = *reinterpret_cast<const float2*>(&hs[rbase + 16][2 * k2]);
            float2 a3 = *reinterpret_cast<const float2*>(&hs[rbase + 24][2 * k2]);
            float2 b0 = *reinterpret_cast<const float2*>(&Wt[c0][2 * k2]);
            float2 b1 = *reinterpret_cast<const float2*>(&Wt[c0 + 1][2 * k2]);
            float2 b2 = *reinterpret_cast<const float2*>(&Wt[c0 + 2][2 * k2]);
            float2 b3 = *reinterpret_cast<const float2*>(&Wt[c0 + 3][2 * k2]);
            acc[0][0] = ffma2(a0, b0, acc[0][0]); acc[0][1] = ffma2(a0, b1, acc[0][1]);
            acc[0][2] = ffma2(a0, b2, acc[0][2]); acc[0][3] = ffma2(a0, b3, acc[0][3]);
            acc[1][0] = ffma2(a1, b0, acc[1][0]); acc[1][1] = ffma2(a1, b1, acc[1][1]);
            acc[1][2] = ffma2(a1, b2, acc[1][2]); acc[1][3] = ffma2(a1, b3, acc[1][3]);
            acc[2][0] = ffma2(a2, b0, acc[2][0]); acc[2][1] = ffma2(a2, b1, acc[2][1]);
            acc[2][2] = ffma2(a2, b2, acc[2][2]); acc[2][3] = ffma2(a2, b3, acc[2][3]);
            acc[3][0] = ffma2(a3, b0, acc[3][0]); acc[3][1] = ffma2(a3, b1, acc[3][1]);
            acc[3][2] = ffma2(a3, b2, acc[3][2]); acc[3][3] = ffma2(a3, b3, acc[3][3]);
        }

        #pragma unroll
        for (int i = 0; i < 4; i++) {
            int r = r0 + rbase + 8 * i;
            if (r < NN) {
                float dv = scale_dinv ? g_dinv[r] : 1.f;
                float4 o;
                o.x = (acc[i][0].x + acc[i][0].y + bb.x) * dv;
                o.y = (acc[i][1].x + acc[i][1].y + bb.y) * dv;
                o.z = (acc[i][2].x + acc[i][2].y + bb.z) * dv;
                o.w = (acc[i][3].x + acc[i][3].y + bb.w) * dv;
                *reinterpret_cast<float4*>(&out[r * 64 + c0]) = o;
            }
        }
    }
}

// ---- aggregation: 2 warps/node, 3-deep pipeline (gather n | idx n+1 | meta n+2) ----
__global__ __launch_bounds__(256, 3) void k_agg(const float* __restrict__ bias, int layer) {
    int lane = threadIdx.x & 31;
    int wrp  = threadIdx.x >> 5;
    int gw   = blockIdx.x * 8 + wrp;
    int half = gw & 1;
    int f    = half * 32 + lane;
    const float* __restrict__ h = g_bufB;
    float bb = bias[f];
    float psum = 0.f, psq = 0.f;
    int node   = gw >> 1;
    int stride = (gridDim.x * 8) >> 1;

    int beg0 = 0, cnt0 = 0; float di0 = 0.f;   // meta(n)
    int beg1 = 0, cnt1 = 0; float di1 = 0.f;   // meta(n+1)
    int idx[16];                                // indices(n)

    if (node < NN) {
        beg0 = g_ptr[node] + g_bsums[node >> 8];
        cnt0 = g_counts[node];
        di0  = g_dinv[node];
        int n1 = node + stride;
        if (n1 < NN) {
            beg1 = g_ptr[n1] + g_bsums[n1 >> 8];
            cnt1 = g_counts[n1];
            di1  = g_dinv[n1];
        }
        int m = cnt0 < 16 ? cnt0 : 16;
        #pragma unroll
        for (int t = 0; t < 16; t++)
            if (t < m) idx[t] = g_csr[beg0 + t];
    }

    while (node < NN) {
        int n1 = node + stride;
        int n2 = n1 + stride;

        // issue gathers for current node (MLP=16) + self row
        int m = cnt0 < 16 ? cnt0 : 16;
        float v[16];
        #pragma unroll
        for (int t = 0; t < 16; t++)
            v[t] = (t < m) ? h[idx[t] * 64 + f] : 0.f;
        float hself = h[node * 64 + f];

        // overlap: prefetch meta(n+2)
        int beg2 = 0, cnt2 = 0; float di2 = 0.f;
        if (n2 < NN) {
            beg2 = g_ptr[n2] + g_bsums[n2 >> 8];
            cnt2 = g_counts[n2];
            di2  = g_dinv[n2];
        }
        // overlap: prefetch indices(n+1)
        int idxn[16];
        if (n1 < NN) {
            int m1 = cnt1 < 16 ? cnt1 : 16;
            #pragma unroll
            for (int t = 0; t < 16; t++)
                if (t < m1) idxn[t] = g_csr[beg1 + t];
        }

        // reduce
        float a0 = 0.f, a1 = 0.f, a2 = 0.f, a3 = 0.f;
        #pragma unroll
        for (int t = 0; t < 16; t += 4) {
            a0 += v[t]; a1 += v[t + 1]; a2 += v[t + 2]; a3 += v[t + 3];
        }
        for (int t = 16; t < cnt0; t++)        // rare deg>16 tail
            a0 += h[g_csr[beg0 + t] * 64 + f];
        float acc = ((a0 + a1) + (a2 + a3)) + hself;
        acc = di0 * acc + bb;
        g_bufA[node * 64 + f] = acc;
        psum += acc;
        psq  += acc * acc;

        // rotate pipeline
        node = n1;
        beg0 = beg1; cnt0 = cnt1; di0 = di1;
        beg1 = beg2; cnt1 = cnt2; di1 = di2;
        #pragma unroll
        for (int t = 0; t < 16; t++) idx[t] = idxn[t];
    }

    __shared__ float ssum[64], ssq[64];
    if (threadIdx.x < 64) { ssum[threadIdx.x] = 0.f; ssq[threadIdx.x] = 0.f; }
    __syncthreads();
    atomicAdd(&ssum[f], psum);
    atomicAdd(&ssq[f],  psq);
    __syncthreads();
    if (threadIdx.x < 64) {
        atomicAdd(&g_bnsum[layer][threadIdx.x], ssum[threadIdx.x]);
        atomicAdd(&g_bnsq[layer][threadIdx.x],  ssq[threadIdx.x]);
    }
}

// ---------------- Wc = fc1_w @ fc2_w ; bc = fc1_b @ fc2_w + fc2_b ----------------
__global__ void k_combine(const float* __restrict__ fc1w, const float* __restrict__ fc1b,
                          const float* __restrict__ fc2w, const float* __restrict__ fc2b) {
    int idx = blockIdx.x * 256 + threadIdx.x;
    if (idx < 4096) {
        int k = idx >> 6, j = idx & 63;
        float s = 0.f;
        #pragma unroll
        for (int t = 0; t < 64; t++) s += fc1w[k * 64 + t] * fc2w[t * 64 + j];
        g_Wc[idx] = s;
    }
    if (idx < 64) {
        float s = fc2b[idx];
        for (int t = 0; t < 64; t++) s += fc1b[t] * fc2w[t * 64 + idx];
        g_bc[idx] = s;
    }
}

// ---------------- segment max over sorted batch + fused logits ----------------
__global__ void k_segmax(const int* __restrict__ batch,
                         const float* __restrict__ fc3w, const float* __restrict__ fc3b,
                         float* __restrict__ ge, float* __restrict__ logits) {
    int g = blockIdx.x;
    int j = threadIdx.x, ty = threadIdx.y;     // (64,4)
    int lo = 0, hi = NN;
    while (lo < hi) { int m = (lo + hi) >> 1; if (batch[m] < g) lo = m + 1; else hi = m; }
    int start = lo;
    hi = NN;
    while (lo < hi) { int m = (lo + hi) >> 1; if (batch[m] < g + 1) lo = m + 1; else hi = m; }
    int end = lo;
    float mv = -INFINITY;
    for (int r = start + ty; r < end; r += 4)
        mv = fmaxf(mv, g_bufB[r * 64 + j]);
    __shared__ float red[4][64];
    red[ty][j] = mv;
    __syncthreads();
    if (ty == 0) {
        mv = fmaxf(fmaxf(red[0][j], red[1][j]), fmaxf(red[2][j], red[3][j]));
        ge[g * 64 + j] = mv;
        red[0][j] = mv;
    }
    __syncthreads();
    if (ty == 0 && j < 32) {
        float v0 = red[0][j], v1 = red[0][j + 32];
        float p0 = v0 * fc3w[2 * j]     + v1 * fc3w[2 * (j + 32)];
        float p1 = v0 * fc3w[2 * j + 1] + v1 * fc3w[2 * (j + 32) + 1];
        #pragma unroll
        for (int o = 16; o; o >>= 1) {
            p0 += __shfl_down_sync(0xFFFFFFFFu, p0, o);
            p1 += __shfl_down_sync(0xFFFFFFFFu, p1, o);
        }
        if (j == 0) {
            float l0 = p0 + fc3b[0], l1 = p1 + fc3b[1];
            float m = fmaxf(l0, l1);
            float lse = m + logf(expf(l0 - m) + expf(l1 - m));
            logits[g * 2]     = l0 - lse;
            logits[g * 2 + 1] = l1 - lse;
        }
    }
}

// zero counts + BN stats for the NEXT invocation (identical work every call)
__global__ void k_cleanup() {
    int i = blockIdx.x * 256 + threadIdx.x;
    if (i < NN) g_counts[i] = 0;
    if (blockIdx.x == 0 && threadIdx.x < 192) {
        ((float*)g_bnsum)[threadIdx.x] = 0.f;
        ((float*)g_bnsq)[threadIdx.x]  = 0.f;
    }
}

// ---------------- launch ----------------
extern "C" void kernel_launch(void* const* d_in, const int* in_sizes, int n_in,
                              void* d_out, int out_size) {
    const float* x      = (const float*)d_in[0];
    const int*   ei     = (const int*)d_in[1];
    const int*   batch  = (const int*)d_in[2];
    const float* conv_w = (const float*)d_in[3];
    const float* conv_b = (const float*)d_in[4];
    const float* bn_g   = (const float*)d_in[5];
    const float* bn_b   = (const float*)d_in[6];
    const float* fc1w   = (const float*)d_in[7];
    const float* fc1b   = (const float*)d_in[8];
    const float* fc2w   = (const float*)d_in[9];
    const float* fc2b   = (const float*)d_in[10];
    const float* fc3w   = (const float*)d_in[11];
    const float* fc3b   = (const float*)d_in[12];

    float* out     = (float*)d_out;
    float* emb_out = out;                         // [N,64]
    float* ge_out  = out + (size_t)NN * 64;       // [G,64]
    float* logits  = ge_out + (size_t)GG * 64;    // [G,2]

    const int NB_N  = (NN + 255) / 256;           // 391
    const int NB_E4 = (EE / 4 + 255) / 256;       // 1172
    dim3 b64x4(64, 4);

    k_hist<<<NB_E4, 256>>>(ei);
    k_scan1<<<NB_N, 256>>>();
    k_scan2<<<1, 512>>>(NB_N);
    // profiled slot: first conv GEMM — no CSR dependency
    k_gemm<<<444, 256>>>(x, conv_w, nullptr, nullptr, 1, 0, -1, nullptr);
    k_fill<<<NB_E4, 256>>>(ei);
    k_agg<<<444, 256>>>(conv_b, 0);

    for (int l = 1; l < 3; l++) {
        k_gemm<<<444, 256>>>(x, conv_w + l * 4096,
                             bn_g + (l - 1) * 64, bn_b + (l - 1) * 64,
                             0, 0, l - 1, nullptr);
        k_agg<<<444, 256>>>(conv_b + l * 64, l);
    }
    k_combine<<<16, 256>>>(fc1w, fc1b, fc2w, fc2b);
    k_gemm<<<444, 256>>>(x, nullptr, bn_g + 2 * 64, bn_b + 2 * 64, 0, 1, 2, emb_out);
    k_segmax<<<GG, b64x4>>>(batch, fc3w, fc3b, ge_out, logits);
    k_cleanup<<<NB_N, 256>>>();
}

// round 17
// speedup vs baseline: 1.7170x; 1.0066x over previous
#include <cuda_runtime.h>
#include <math.h>

#define NN 100000
#define EE 1200000
#define GG 128

// ---------------- device scratch (no allocations allowed) ----------------
__device__ __align__(16) float g_bufA[NN * 64];
__device__ __align__(16) float g_bufB[NN * 64];
__device__ int   g_counts[NN];        // real edges per dst (zero at start; re-zeroed in k_segmax)
__device__ int   g_counter[NN];
__device__ int   g_ptr[NN];
__device__ int   g_csr[EE];
__device__ int   g_bsums[512];
__device__ float g_dinv[NN];
__device__ float g_bnsum[3][64];      // per-layer BN stats (zero at start; re-zeroed in k_segmax)
__device__ float g_bnsq[3][64];
__device__ __align__(16) float g_Wc[64 * 64];
__device__ __align__(16) float g_bc[64];

// packed fp32x2 FMA (Blackwell)
__device__ __forceinline__ float2 ffma2(float2 a, float2 b, float2 c) {
    float2 d;
    asm("{\n\t"
        ".reg .b64 ra, rb, rc;\n\t"
        "mov.b64 ra, {%2, %3};\n\t"
        "mov.b64 rb, {%4, %5};\n\t"
        "mov.b64 rc, {%6, %7};\n\t"
        "fma.rn.f32x2 rc, ra, rb, rc;\n\t"
        "mov.b64 {%0, %1}, rc;\n\t"
        "}"
        : "=f"(d.x), "=f"(d.y)
        : "f"(a.x), "f"(a.y), "f"(b.x), "f"(b.y), "f"(c.x), "f"(c.y));
    return d;
}

// ---------------- CSR build (8 edges/thread for MLP on atomic chains) ----------------
__global__ void k_hist(const int* __restrict__ ei) {
    int i = blockIdx.x * 256 + threadIdx.x;
    if (i < EE / 8) {
        int4 d0 = reinterpret_cast<const int4*>(ei + EE)[2 * i];
        int4 d1 = reinterpret_cast<const int4*>(ei + EE)[2 * i + 1];
        atomicAdd(&g_counts[d0.x], 1);
        atomicAdd(&g_counts[d0.y], 1);
        atomicAdd(&g_counts[d0.z], 1);
        atomicAdd(&g_counts[d0.w], 1);
        atomicAdd(&g_counts[d1.x], 1);
        atomicAdd(&g_counts[d1.y], 1);
        atomicAdd(&g_counts[d1.z], 1);
        atomicAdd(&g_counts[d1.w], 1);
    }
}

__device__ __forceinline__ int warp_incl(int v, int lane) {
    #pragma unroll
    for (int o = 1; o < 32; o <<= 1) {
        int t = __shfl_up_sync(0xFFFFFFFFu, v, o);
        if (lane >= o) v += t;
    }
    return v;
}

template <int NW>
__device__ __forceinline__ int block_excl_scan(int v, int tid, int* total) {
    __shared__ int wt[NW];
    int lane = tid & 31, wid = tid >> 5;
    int incl = warp_incl(v, lane);
    if (lane == 31) wt[wid] = incl;
    __syncthreads();
    if (wid == 0) {
        int x = (lane < NW) ? wt[lane] : 0;
        x = warp_incl(x, lane);
        if (lane < NW) wt[lane] = x;
    }
    __syncthreads();
    int off = wid ? wt[wid - 1] : 0;
    *total = wt[NW - 1];
    return off + incl - v;
}

__global__ void k_scan1() {
    int tid = threadIdx.x;
    int i = blockIdx.x * 256 + tid;
    int v = (i < NN) ? g_counts[i] : 0;
    if (i < NN) {
        g_dinv[i] = rsqrtf((float)(v + 1)); // +1 self loop
        g_counter[i] = 0;
    }
    int total;
    int e = block_excl_scan<8>(v, tid, &total);
    if (i < NN) g_ptr[i] = e;
    if (tid == 0) g_bsums[blockIdx.x] = total;
}

__global__ void k_scan2(int nb) {
    int tid = threadIdx.x;
    int v = (tid < nb) ? g_bsums[tid] : 0;
    int total;
    int e = block_excl_scan<16>(v, tid, &total);
    if (tid < nb) g_bsums[tid] = e;
}

__device__ __forceinline__ void fill_one(int d, int s) {
    int p = g_ptr[d] + g_bsums[d >> 8] + atomicAdd(&g_counter[d], 1);
    g_csr[p] = s;
}

__global__ void k_fill(const int* __restrict__ ei) {
    int i = blockIdx.x * 256 + threadIdx.x;
    if (i < EE / 8) {
        int4 d0 = reinterpret_cast<const int4*>(ei + EE)[2 * i];
        int4 d1 = reinterpret_cast<const int4*>(ei + EE)[2 * i + 1];
        int4 s0 = reinterpret_cast<const int4*>(ei)[2 * i];
        int4 s1 = reinterpret_cast<const int4*>(ei)[2 * i + 1];
        fill_one(d0.x, s0.x);
        fill_one(d0.y, s0.y);
        fill_one(d0.z, s0.z);
        fill_one(d0.w, s0.w);
        fill_one(d1.x, s1.x);
        fill_one(d1.y, s1.y);
        fill_one(d1.z, s1.z);
        fill_one(d1.w, s1.w);
    }
}

// ------ register-tiled GEMM (non-persistent, tile per block — measured best) ------
// Block tile 64x64, warp tile 32x16, thread tile 4x4 (f32x2 paired over K).
__global__ __launch_bounds__(256, 3) void k_gemm(
    const float* __restrict__ xin,
    const float* __restrict__ Wext,
    const float* __restrict__ gma,
    const float* __restrict__ bta,
    int src0, int use_wc, int bn_layer,   // bn_layer < 0: no activation
    float* __restrict__ emb_out)
{
    const float* __restrict__ hin = src0 ? xin : g_bufA;
    const float* __restrict__ W   = use_wc ? g_Wc : Wext;
    float* __restrict__ out = g_bufB;

    __shared__ float hs[64][68];   // pad 68: conflict-free f2 a-loads, f4-aligned stage
    __shared__ float Wt[64][66];   // transposed weights, pad 66: conflict-free b-loads

    int tid = threadIdx.x;

    // stage transposed weights: Wt[c][k] = W[k][c]
    #pragma unroll
    for (int t = 0; t < 16; t++) {
        int idx = tid + t * 256;
        Wt[idx & 63][idx >> 6] = W[idx];
    }

    // BN scale/shift for the 4 input columns this thread stages
    int cq = (tid & 15) * 4;
    float sc0 = 1.f, sc1 = 1.f, sc2 = 1.f, sc3 = 1.f;
    float sh0 = 0.f, sh1 = 0.f, sh2 = 0.f, sh3 = 0.f;
    if (bn_layer >= 0) {
        float mu, var, istd;
        mu = g_bnsum[bn_layer][cq] * (1.0f / NN);
        var = g_bnsq[bn_layer][cq] * (1.0f / NN) - mu * mu;
        istd = rsqrtf(var + 1e-5f); sc0 = istd * gma[cq];     sh0 = bta[cq]     - mu * sc0;
        mu = g_bnsum[bn_layer][cq + 1] * (1.0f / NN);
        var = g_bnsq[bn_layer][cq + 1] * (1.0f / NN) - mu * mu;
        istd = rsqrtf(var + 1e-5f); sc1 = istd * gma[cq + 1]; sh1 = bta[cq + 1] - mu * sc1;
        mu = g_bnsum[bn_layer][cq + 2] * (1.0f / NN);
        var = g_bnsq[bn_layer][cq + 2] * (1.0f / NN) - mu * mu;
        istd = rsqrtf(var + 1e-5f); sc2 = istd * gma[cq + 2]; sh2 = bta[cq + 2] - mu * sc2;
        mu = g_bnsum[bn_layer][cq + 3] * (1.0f / NN);
        var = g_bnsq[bn_layer][cq + 3] * (1.0f / NN) - mu * mu;
        istd = rsqrtf(var + 1e-5f); sc3 = istd * gma[cq + 3]; sh3 = bta[cq + 3] - mu * sc3;
    }

    // stage input tile (64 rows x 64 cols), fused BN+ReLU, optional emb_out
    int r0 = blockIdx.x * 64;
    int srow = tid >> 4;              // 0..15; rows srow + 16*i
    #pragma unroll
    for (int i = 0; i < 4; i++) {
        int row = srow + 16 * i;
        int r = r0 + row;
        if (r < NN) {
            float4 v = *reinterpret_cast<const float4*>(&hin[r * 64 + cq]);
            if (bn_layer >= 0) {
                v.x = fmaxf(v.x * sc0 + sh0, 0.f);
                v.y = fmaxf(v.y * sc1 + sh1, 0.f);
                v.z = fmaxf(v.z * sc2 + sh2, 0.f);
                v.w = fmaxf(v.w * sc3 + sh3, 0.f);
            }
            *reinterpret_cast<float4*>(&hs[row][cq]) = v;
            if (emb_out) *reinterpret_cast<float4*>(&emb_out[r * 64 + cq]) = v;
        }
    }
    __syncthreads();

    // outer-product compute
    int w = tid >> 5, lane = tid & 31;
    int ry = lane >> 2, cx = lane & 3;
    int rbase = (w & 1) * 32 + ry;          // thread rows: rbase + 8*i
    int c0 = (w >> 1) * 16 + cx * 4;        // thread cols: c0..c0+3

    float2 acc[4][4];
    #pragma unroll
    for (int i = 0; i < 4; i++)
        #pragma unroll
        for (int j = 0; j < 4; j++)
            acc[i][j] = make_float2(0.f, 0.f);

    #pragma unroll 4
    for (int k2 = 0; k2 < 32; k2++) {
        float2 a0 = *reinterpret_cast<const float2*>(&hs[rbase][2 * k2]);
        float2 a1 = *reinterpret_cast<const float2*>(&hs[rbase + 8][2 * k2]);
        float2 a2 = *reinterpret_cast<const float2*>(&hs[rbase + 16][2 * k2]);
        float2 a3 = *reinterpret_cast<const float2*>(&hs[rbase + 24][2 * k2]);
        float2 b0 = *reinterpret_cast<const float2*>(&Wt[c0][2 * k2]);
        float2 b1 = *reinterpret_cast<const float2*>(&Wt[c0 + 1][2 * k2]);
        float2 b2 = *reinterpret_cast<const float2*>(&Wt[c0 + 2][2 * k2]);
        float2 b3 = *reinterpret_cast<const float2*>(&Wt[c0 + 3][2 * k2]);
        acc[0][0] = ffma2(a0, b0, acc[0][0]); acc[0][1] = ffma2(a0, b1, acc[0][1]);
        acc[0][2] = ffma2(a0, b2, acc[0][2]); acc[0][3] = ffma2(a0, b3, acc[0][3]);
        acc[1][0] = ffma2(a1, b0, acc[1][0]); acc[1][1] = ffma2(a1, b1, acc[1][1]);
        acc[1][2] = ffma2(a1, b2, acc[1][2]); acc[1][3] = ffma2(a1, b3, acc[1][3]);
        acc[2][0] = ffma2(a2, b0, acc[2][0]); acc[2][1] = ffma2(a2, b1, acc[2][1]);
        acc[2][2] = ffma2(a2, b2, acc[2][2]); acc[2][3] = ffma2(a2, b3, acc[2][3]);
        acc[3][0] = ffma2(a3, b0, acc[3][0]); acc[3][1] = ffma2(a3, b1, acc[3][1]);
        acc[3][2] = ffma2(a3, b2, acc[3][2]); acc[3][3] = ffma2(a3, b3, acc[3][3]);
    }

    float4 bb = make_float4(0.f, 0.f, 0.f, 0.f);
    if (use_wc) bb = *reinterpret_cast<const float4*>(&g_bc[c0]);
    const int scale_dinv = !use_wc;

    #pragma unroll
    for (int i = 0; i < 4; i++) {
        int r = r0 + rbase + 8 * i;
        if (r < NN) {
            float dv = scale_dinv ? g_dinv[r] : 1.f;
            float4 o;
            o.x = (acc[i][0].x + acc[i][0].y + bb.x) * dv;
            o.y = (acc[i][1].x + acc[i][1].y + bb.y) * dv;
            o.z = (acc[i][2].x + acc[i][2].y + bb.z) * dv;
            o.w = (acc[i][3].x + acc[i][3].y + bb.w) * dv;
            *reinterpret_cast<float4*>(&out[r * 64 + c0]) = o;
        }
    }
}

// ---- aggregation: 2 warps/node, 3-deep pipeline (gather n | idx n+1 | meta n+2) ----
__global__ __launch_bounds__(256, 3) void k_agg(const float* __restrict__ bias, int layer) {
    int lane = threadIdx.x & 31;
    int wrp  = threadIdx.x >> 5;
    int gw   = blockIdx.x * 8 + wrp;
    int half = gw & 1;
    int f    = half * 32 + lane;
    const float* __restrict__ h = g_bufB;
    float bb = bias[f];
    float psum = 0.f, psq = 0.f;
    int node   = gw >> 1;
    int stride = (gridDim.x * 8) >> 1;

    int beg0 = 0, cnt0 = 0; float di0 = 0.f;   // meta(n)
    int beg1 = 0, cnt1 = 0; float di1 = 0.f;   // meta(n+1)
    int idx[16];                                // indices(n)

    if (node < NN) {
        beg0 = g_ptr[node] + g_bsums[node >> 8];
        cnt0 = g_counts[node];
        di0  = g_dinv[node];
        int n1 = node + stride;
        if (n1 < NN) {
            beg1 = g_ptr[n1] + g_bsums[n1 >> 8];
            cnt1 = g_counts[n1];
            di1  = g_dinv[n1];
        }
        int m = cnt0 < 16 ? cnt0 : 16;
        #pragma unroll
        for (int t = 0; t < 16; t++)
            if (t < m) idx[t] = g_csr[beg0 + t];
    }

    while (node < NN) {
        int n1 = node + stride;
        int n2 = n1 + stride;

        // issue gathers for current node (MLP=16) + self row
        int m = cnt0 < 16 ? cnt0 : 16;
        float v[16];
        #pragma unroll
        for (int t = 0; t < 16; t++)
            v[t] = (t < m) ? h[idx[t] * 64 + f] : 0.f;
        float hself = h[node * 64 + f];

        // overlap: prefetch meta(n+2)
        int beg2 = 0, cnt2 = 0; float di2 = 0.f;
        if (n2 < NN) {
            beg2 = g_ptr[n2] + g_bsums[n2 >> 8];
            cnt2 = g_counts[n2];
            di2  = g_dinv[n2];
        }
        // overlap: prefetch indices(n+1)
        int idxn[16];
        if (n1 < NN) {
            int m1 = cnt1 < 16 ? cnt1 : 16;
            #pragma unroll
            for (int t = 0; t < 16; t++)
                if (t < m1) idxn[t] = g_csr[beg1 + t];
        }

        // reduce
        float a0 = 0.f, a1 = 0.f, a2 = 0.f, a3 = 0.f;
        #pragma unroll
        for (int t = 0; t < 16; t += 4) {
            a0 += v[t]; a1 += v[t + 1]; a2 += v[t + 2]; a3 += v[t + 3];
        }
        for (int t = 16; t < cnt0; t++)        // rare deg>16 tail
            a0 += h[g_csr[beg0 + t] * 64 + f];
        float acc = ((a0 + a1) + (a2 + a3)) + hself;
        acc = di0 * acc + bb;
        g_bufA[node * 64 + f] = acc;
        psum += acc;
        psq  += acc * acc;

        // rotate pipeline
        node = n1;
        beg0 = beg1; cnt0 = cnt1; di0 = di1;
        beg1 = beg2; cnt1 = cnt2; di1 = di2;
        #pragma unroll
        for (int t = 0; t < 16; t++) idx[t] = idxn[t];
    }

    __shared__ float ssum[64], ssq[64];
    if (threadIdx.x < 64) { ssum[threadIdx.x] = 0.f; ssq[threadIdx.x] = 0.f; }
    __syncthreads();
    atomicAdd(&ssum[f], psum);
    atomicAdd(&ssq[f],  psq);
    __syncthreads();
    if (threadIdx.x < 64) {
        atomicAdd(&g_bnsum[layer][threadIdx.x], ssum[threadIdx.x]);
        atomicAdd(&g_bnsq[layer][threadIdx.x],  ssq[threadIdx.x]);
    }
}

// ---------------- Wc = fc1_w @ fc2_w ; bc = fc1_b @ fc2_w + fc2_b ----------------
__global__ void k_combine(const float* __restrict__ fc1w, const float* __restrict__ fc1b,
                          const float* __restrict__ fc2w, const float* __restrict__ fc2b) {
    int idx = blockIdx.x * 256 + threadIdx.x;
    if (idx < 4096) {
        int k = idx >> 6, j = idx & 63;
        float s = 0.f;
        #pragma unroll
        for (int t = 0; t < 64; t++) s += fc1w[k * 64 + t] * fc2w[t * 64 + j];
        g_Wc[idx] = s;
    }
    if (idx < 64) {
        float s = fc2b[idx];
        for (int t = 0; t < 64; t++) s += fc1b[t] * fc2w[t * 64 + idx];
        g_bc[idx] = s;
    }
}

// ------ segment max over sorted batch + fused logits + cleanup for next call ------
__global__ void k_segmax(const int* __restrict__ batch,
                         const float* __restrict__ fc3w, const float* __restrict__ fc3b,
                         float* __restrict__ ge, float* __restrict__ logits) {
    int g = blockIdx.x;
    int j = threadIdx.x, ty = threadIdx.y;     // (64,4)
    int tf = ty * 64 + j;                      // flat tid 0..255

    // cleanup for NEXT invocation (counts + BN stats have no remaining consumers)
    for (int i = g * 256 + tf; i < NN; i += GG * 256) g_counts[i] = 0;
    if (g == 0 && tf < 192) {
        ((float*)g_bnsum)[tf] = 0.f;
        ((float*)g_bnsq)[tf]  = 0.f;
    }

    int lo = 0, hi = NN;
    while (lo < hi) { int m = (lo + hi) >> 1; if (batch[m] < g) lo = m + 1; else hi = m; }
    int start = lo;
    hi = NN;
    while (lo < hi) { int m = (lo + hi) >> 1; if (batch[m] < g + 1) lo = m + 1; else hi = m; }
    int end = lo;
    float mv = -INFINITY;
    for (int r = start + ty; r < end; r += 4)
        mv = fmaxf(mv, g_bufB[r * 64 + j]);
    __shared__ float red[4][64];
    red[ty][j] = mv;
    __syncthreads();
    if (ty == 0) {
        mv = fmaxf(fmaxf(red[0][j], red[1][j]), fmaxf(red[2][j], red[3][j]));
        ge[g * 64 + j] = mv;
        red[0][j] = mv;
    }
    __syncthreads();
    if (ty == 0 && j < 32) {
        float v0 = red[0][j], v1 = red[0][j + 32];
        float p0 = v0 * fc3w[2 * j]     + v1 * fc3w[2 * (j + 32)];
        float p1 = v0 * fc3w[2 * j + 1] + v1 * fc3w[2 * (j + 32) + 1];
        #pragma unroll
        for (int o = 16; o; o >>= 1) {
            p0 += __shfl_down_sync(0xFFFFFFFFu, p0, o);
            p1 += __shfl_down_sync(0xFFFFFFFFu, p1, o);
        }
        if (j == 0) {
            float l0 = p0 + fc3b[0], l1 = p1 + fc3b[1];
            float m = fmaxf(l0, l1);
            float lse = m + logf(expf(l0 - m) + expf(l1 - m));
            logits[g * 2]     = l0 - lse;
            logits[g * 2 + 1] = l1 - lse;
        }
    }
}

// ---------------- launch ----------------
extern "C" void kernel_launch(void* const* d_in, const int* in_sizes, int n_in,
                              void* d_out, int out_size) {
    const float* x      = (const float*)d_in[0];
    const int*   ei     = (const int*)d_in[1];
    const int*   batch  = (const int*)d_in[2];
    const float* conv_w = (const float*)d_in[3];
    const float* conv_b = (const float*)d_in[4];
    const float* bn_g   = (const float*)d_in[5];
    const float* bn_b   = (const float*)d_in[6];
    const float* fc1w   = (const float*)d_in[7];
    const float* fc1b   = (const float*)d_in[8];
    const float* fc2w   = (const float*)d_in[9];
    const float* fc2b   = (const float*)d_in[10];
    const float* fc3w   = (const float*)d_in[11];
    const float* fc3b   = (const float*)d_in[12];

    float* out     = (float*)d_out;
    float* emb_out = out;                         // [N,64]
    float* ge_out  = out + (size_t)NN * 64;       // [G,64]
    float* logits  = ge_out + (size_t)GG * 64;    // [G,2]

    const int NB_N  = (NN + 255) / 256;           // 391
    const int NB_E8 = (EE / 8 + 255) / 256;       // 586
    const int NB_G  = (NN + 63) / 64;             // 1563
    dim3 b64x4(64, 4);

    k_hist<<<NB_E8, 256>>>(ei);
    k_scan1<<<NB_N, 256>>>();
    k_scan2<<<1, 512>>>(NB_N);
    // profiled slot (#4): k_fill — CSR bucket scatter, 8 chains/thread
    k_fill<<<NB_E8, 256>>>(ei);
    k_gemm<<<NB_G, 256>>>(x, conv_w, nullptr, nullptr, 1, 0, -1, nullptr);
    k_agg<<<444, 256>>>(conv_b, 0);

    for (int l = 1; l < 3; l++) {
        k_gemm<<<NB_G, 256>>>(x, conv_w + l * 4096,
                              bn_g + (l - 1) * 64, bn_b + (l - 1) * 64,
                              0, 0, l - 1, nullptr);
        k_agg<<<444, 256>>>(conv_b + l * 64, l);
    }
    k_combine<<<16, 256>>>(fc1w, fc1b, fc2w, fc2b);
    k_gemm<<<NB_G, 256>>>(x, nullptr, bn_g + 2 * 64, bn_b + 2 * 64, 0, 1, 2, emb_out);
    k_segmax<<<GG, b64x4>>>(batch, fc3w, fc3b, ge_out, logits);
}